// round 12
// baseline (speedup 1.0000x reference)
#include <cuda_runtime.h>
#include <cuda_fp16.h>

#define NN 100000
#define EE 1600000
#define ET (EE + NN)
#define GG 2048
#define NBLK ((NN + 1023) / 1024)
#define WPB 8
#define XSTR 132   // 64 nodes * 2 (dup) + 4 pad floats

typedef unsigned long long u64;

// ---------------- scratch (device globals; no allocation) ----------------
__device__ __align__(16) __half g_Hh[(size_t)NN * 64];  // fp16 transformed features
__device__ __align__(16) float  g_A[(size_t)NN * 64];   // aggregated output
__device__ __align__(16) float  g_als[NN * 4];
__device__ __align__(16) float  g_ald[NN * 4];
__device__ int g_deg[NN];       // zero-initialized at load; re-zeroed by pool_kernel
__device__ int g_scan[NN];
__device__ int g_rowptr[NN];
__device__ int g_bsum[NBLK];
__device__ int g_rank[ET];      // per-edge rank within its dst bucket
__device__ int g_csrc[ET];

__device__ __forceinline__ float lrelu(float x) { return x > 0.f ? x : 0.2f * x; }

// f32x2 packed FMA (Blackwell FFMA2)
__device__ __forceinline__ void fma2(u64& d, u64 a, u64 b) {
    asm("fma.rn.f32x2 %0,%1,%2,%0;" : "+l"(d) : "l"(a), "l"(b));
}
__device__ __forceinline__ float2 unpack2(u64 v) {
    float x, y; asm("mov.b64 {%0,%1},%2;" : "=f"(x), "=f"(y) : "l"(v));
    return make_float2(x, y);
}

// ---------------- CSR build ----------------
// g_deg must be zero at entry: zero-init at load, re-zeroed by pool_kernel.
__global__ void hist_kernel(const int* __restrict__ ei) {
    int i = blockIdx.x * blockDim.x + threadIdx.x;
    if (i >= ET) return;
    int dst = (i < EE) ? ei[EE + i] : (i - EE);
    g_rank[i] = atomicAdd(&g_deg[dst], 1);
}

__global__ void scan1_kernel() {
    __shared__ int buf[1024];
    int t = threadIdx.x;
    int i = blockIdx.x * 1024 + t;
    int v = (i < NN) ? g_deg[i] : 0;
    buf[t] = v;
    __syncthreads();
    for (int off = 1; off < 1024; off <<= 1) {
        int add = (t >= off) ? buf[t - off] : 0;
        __syncthreads();
        buf[t] += add;
        __syncthreads();
    }
    if (i < NN) g_scan[i] = buf[t];
    if (t == 1023) g_bsum[blockIdx.x] = buf[1023];
}

// fused scan2+scan3: each block re-scans the 98 block sums locally
__global__ void scan3_kernel() {
    __shared__ int sb[128];
    __shared__ int ex[128];
    int t = threadIdx.x;
    int v0 = 0;
    if (t < 128) {
        v0 = (t < NBLK) ? g_bsum[t] : 0;
        sb[t] = v0;
    }
    __syncthreads();
    for (int off = 1; off < 128; off <<= 1) {
        int add = (t < 128 && t >= off) ? sb[t - off] : 0;
        __syncthreads();
        if (t < 128) sb[t] += add;
        __syncthreads();
    }
    if (t < 128) ex[t] = sb[t] - v0;  // exclusive
    __syncthreads();

    int i = blockIdx.x * blockDim.x + t;
    if (i >= NN) return;
    g_rowptr[i] = g_scan[i] - g_deg[i] + ex[i >> 10];  // exclusive prefix
}

// atomic-free scatter using precomputed ranks
__global__ void scatter_kernel(const int* __restrict__ ei) {
    int i = blockIdx.x * blockDim.x + threadIdx.x;
    if (i >= ET) return;
    int src, dst;
    if (i < EE) { src = ei[i]; dst = ei[EE + i]; }
    else        { src = i - EE; dst = i - EE; }
    g_csrc[g_rowptr[dst] + g_rank[i]] = src;
}

// ---------------- fused GEMM + attention logits (dup-X, K-chunk 32) --------
// Block: 256 threads, tile 64 nodes x 64 channels, K in chunks of 32.
// Thread (c4 = tid&15, n4 = tid>>4) computes nodes [4*n4,4*n4+4) x ch [4*c4,4*c4+4).
// X stored pre-duplicated ((v,v) float2 per node-k) -> inner loop is
// 1 W-LDS.128 + 2 X-LDS.128 + 8 FFMA2 per k, zero packing MOVs.
template <int FIN, bool FROM_A>
__global__ void __launch_bounds__(256)
gemm_attn_kernel(const float* __restrict__ xin_ext,
                 const float* __restrict__ W,
                 const float* __restrict__ a_src,
                 const float* __restrict__ a_dst,
                 const float* __restrict__ pbias) {
    constexpr int NCH = FIN / 32;                    // K chunks
    __shared__ __align__(16) float Ws[32 * 64];      // W chunk [k][64]
    __shared__ __align__(16) float Xt[32 * XSTR];    // x chunk, dup pairs [k][2*node]
    __shared__ float Aat[128];                       // [0:64) a_src, [64:128) a_dst
    __shared__ float Pb[FIN];

    int tid = threadIdx.x;
    int nbase = blockIdx.x * 64;
    int c4 = tid & 15;
    int n4 = tid >> 4;

    if (tid < 64)       Aat[tid] = a_src[tid];
    else if (tid < 128) Aat[tid] = a_dst[tid - 64];
    if (FROM_A) {
        for (int i = tid; i < FIN; i += 256) Pb[i] = pbias[i];
    }

    const float* xin = FROM_A ? (const float*)g_A : xin_ext;

    u64 acc[8];
#pragma unroll
    for (int j = 0; j < 8; j++) acc[j] = 0ull;

    for (int ch = 0; ch < NCH; ch++) {
        __syncthreads();
        // load W chunk (32 rows x 64 ch): 8 floats per thread
        for (int i = tid; i < 32 * 64; i += 256) Ws[i] = W[ch * 32 * 64 + i];
        // stage x chunk duplicated: idx -> (node = idx&63, k4 = idx>>6 in 0..7)
        for (int idx = tid; idx < 64 * 8; idx += 256) {
            int node = idx & 63;
            int k4 = idx >> 6;
            int gn = nbase + node;
            float4 v = make_float4(0.f, 0.f, 0.f, 0.f);
            if (gn < NN)
                v = reinterpret_cast<const float4*>(xin + (size_t)gn * FIN)[ch * 8 + k4];
            if (FROM_A) {
                v.x = fmaxf(v.x + Pb[ch * 32 + 4 * k4 + 0], 0.f);
                v.y = fmaxf(v.y + Pb[ch * 32 + 4 * k4 + 1], 0.f);
                v.z = fmaxf(v.z + Pb[ch * 32 + 4 * k4 + 2], 0.f);
                v.w = fmaxf(v.w + Pb[ch * 32 + 4 * k4 + 3], 0.f);
            }
            reinterpret_cast<float2*>(&Xt[(4 * k4 + 0) * XSTR])[node] = make_float2(v.x, v.x);
            reinterpret_cast<float2*>(&Xt[(4 * k4 + 1) * XSTR])[node] = make_float2(v.y, v.y);
            reinterpret_cast<float2*>(&Xt[(4 * k4 + 2) * XSTR])[node] = make_float2(v.z, v.z);
            reinterpret_cast<float2*>(&Xt[(4 * k4 + 3) * XSTR])[node] = make_float2(v.w, v.w);
        }
        __syncthreads();

#pragma unroll 4
        for (int k = 0; k < 32; k++) {
            double2 wd = *reinterpret_cast<const double2*>(&Ws[k * 64 + c4 * 4]);
            const double2* xp =
                reinterpret_cast<const double2*>(&Xt[k * XSTR + n4 * 8]);
            double2 xa = xp[0], xb = xp[1];
            u64 w0 = (u64)__double_as_longlong(wd.x);
            u64 w1 = (u64)__double_as_longlong(wd.y);
            u64 x0 = (u64)__double_as_longlong(xa.x);
            u64 x1 = (u64)__double_as_longlong(xa.y);
            u64 x2 = (u64)__double_as_longlong(xb.x);
            u64 x3 = (u64)__double_as_longlong(xb.y);
            fma2(acc[0], x0, w0); fma2(acc[1], x0, w1);
            fma2(acc[2], x1, w0); fma2(acc[3], x1, w1);
            fma2(acc[4], x2, w0); fma2(acc[5], x2, w1);
            fma2(acc[6], x3, w0); fma2(acc[7], x3, w1);
        }
    }

    // ---- epilogue (same acc mapping as R7) ----
    int head = c4 >> 2;
    int cq = c4 & 3;
    float As0 = Aat[c4 * 4 + 0], As1 = Aat[c4 * 4 + 1];
    float As2 = Aat[c4 * 4 + 2], As3 = Aat[c4 * 4 + 3];
    float Ad0 = Aat[64 + c4 * 4 + 0], Ad1 = Aat[64 + c4 * 4 + 1];
    float Ad2 = Aat[64 + c4 * 4 + 2], Ad3 = Aat[64 + c4 * 4 + 3];

#pragma unroll
    for (int nn = 0; nn < 4; nn++) {
        float2 lo = unpack2(acc[nn * 2 + 0]);
        float2 hi = unpack2(acc[nn * 2 + 1]);
        int gn = nbase + n4 * 4 + nn;

        if (gn < NN) {
            __half2 h0 = __floats2half2_rn(lo.x, lo.y);
            __half2 h1 = __floats2half2_rn(hi.x, hi.y);
            uint2 pk;
            pk.x = *reinterpret_cast<unsigned*>(&h0);
            pk.y = *reinterpret_cast<unsigned*>(&h1);
            *reinterpret_cast<uint2*>(g_Hh + (size_t)gn * 64 + c4 * 4) = pk;
        }

        float ss = lo.x * As0 + lo.y * As1 + hi.x * As2 + hi.y * As3;
        float dd = lo.x * Ad0 + lo.y * Ad1 + hi.x * Ad2 + hi.y * Ad3;
        ss += __shfl_xor_sync(0xFFFFFFFFu, ss, 1);
        ss += __shfl_xor_sync(0xFFFFFFFFu, ss, 2);
        dd += __shfl_xor_sync(0xFFFFFFFFu, dd, 1);
        dd += __shfl_xor_sync(0xFFFFFFFFu, dd, 2);
        if (cq == 0 && gn < NN) {
            g_als[gn * 4 + head] = ss;
            g_ald[gn * 4 + head] = dd;
        }
    }
}

// ---------------- fused softmax + aggregation (max-free, gather) -----------
__global__ void __launch_bounds__(256) gat_aggregate_kernel() {
    __shared__ int    s_s[WPB][32];
    __shared__ float4 s_w[WPB][32];

    int w = threadIdx.x >> 5;
    int lane = threadIdx.x & 31;
    int n = blockIdx.x * WPB + w;
    if (n >= NN) return;

    int beg = g_rowptr[n];
    int deg = g_deg[n];
    float4 ad = *reinterpret_cast<const float4*>(g_ald + n * 4);

    int head = lane >> 3;          // lane owns channels (2*lane, 2*lane+1)
    float accx = 0.f, accy = 0.f;
    float swh = 0.f;               // this lane's head exp-sum

    const __half2* Hp = reinterpret_cast<const __half2*>(g_Hh);

    if (deg <= 32) {
        // ---- fast path: one gather, one chunk, no max phase ----
        if (lane < deg) {
            int s_reg = g_csrc[beg + lane];
            float4 a = *reinterpret_cast<const float4*>(g_als + s_reg * 4);
            float4 wv;
            wv.x = __expf(lrelu(a.x + ad.x));
            wv.y = __expf(lrelu(a.y + ad.y));
            wv.z = __expf(lrelu(a.z + ad.z));
            wv.w = __expf(lrelu(a.w + ad.w));
            s_s[w][lane] = s_reg;
            s_w[w][lane] = wv;
        }
        __syncwarp();

        const float* wp = reinterpret_cast<const float*>(&s_w[w][0]);
#pragma unroll 8
        for (int j = 0; j < deg; j++) {
            int s0 = s_s[w][j];
            float w0 = wp[j * 4 + head];
            swh += w0;
            float2 f = __half22float2(Hp[(size_t)s0 * 32 + lane]);
            accx = fmaf(w0, f.x, accx);
            accy = fmaf(w0, f.y, accy);
        }
    } else {
        // ---- general path (rare): chunked, no max phase ----
        for (int base = 0; base < deg; base += 32) {
            int i = base + lane;
            if (i < deg) {
                int s = g_csrc[beg + i];
                float4 a = *reinterpret_cast<const float4*>(g_als + s * 4);
                float4 wv;
                wv.x = __expf(lrelu(a.x + ad.x));
                wv.y = __expf(lrelu(a.y + ad.y));
                wv.z = __expf(lrelu(a.z + ad.z));
                wv.w = __expf(lrelu(a.w + ad.w));
                s_s[w][lane] = s;
                s_w[w][lane] = wv;
            }
            __syncwarp();
            int cnt = min(32, deg - base);
            const float* wp = reinterpret_cast<const float*>(&s_w[w][0]);
#pragma unroll 8
            for (int j = 0; j < cnt; j++) {
                int s0 = s_s[w][j];
                float w0 = wp[j * 4 + head];
                swh += w0;
                float2 f = __half22float2(Hp[(size_t)s0 * 32 + lane]);
                accx = fmaf(w0, f.x, accx);
                accy = fmaf(w0, f.y, accy);
            }
            __syncwarp();
        }
    }

    float inv = 1.f / (swh + 1e-16f);
    *reinterpret_cast<float2*>(g_A + (size_t)n * 64 + 2 * lane) =
        make_float2(accx * inv, accy * inv);
}

// ---------------- output init + pooling + head ----------------
__global__ void init_out_kernel(float* out, const float* __restrict__ hb) {
    int g = blockIdx.x * blockDim.x + threadIdx.x;
    if (g < GG) out[g] = hb[0];
}

__global__ void pool_kernel(const float* __restrict__ b2,
                            const float* __restrict__ hw,
                            const int* __restrict__ batch,
                            float* out) {
    __shared__ float sb[64], sw[64];
    int tid = threadIdx.x;
    if (tid < 64) { sb[tid] = b2[tid]; sw[tid] = hw[tid]; }
    __syncthreads();

    long long t = (long long)blockIdx.x * blockDim.x + tid;
    int n = (int)(t >> 5);
    int lane = (int)(t & 31);
    if (n >= NN) return;

    const float* ar = g_A + (size_t)n * 64;
    float sm = fmaxf(ar[lane] + sb[lane], 0.f) * sw[lane]
             + fmaxf(ar[lane + 32] + sb[lane + 32], 0.f) * sw[lane + 32];
#pragma unroll
    for (int off = 16; off > 0; off >>= 1)
        sm += __shfl_down_sync(0xFFFFFFFFu, sm, off);
    if (lane == 0) {
        atomicAdd(&out[batch[n]], sm);
        g_deg[n] = 0;   // restore CSR-build invariant for the next replay
    }
}

// ---------------- launch ----------------
extern "C" void kernel_launch(void* const* d_in, const int* in_sizes, int n_in,
                              void* d_out, int out_size) {
    const float* x     = (const float*)d_in[0];
    const int*   ei    = (const int*)d_in[1];
    const int*   batch = (const int*)d_in[2];
    const float* W0  = (const float*)d_in[3];
    const float* as0 = (const float*)d_in[4];
    const float* ad0 = (const float*)d_in[5];
    const float* b0  = (const float*)d_in[6];
    const float* W1  = (const float*)d_in[7];
    const float* as1 = (const float*)d_in[8];
    const float* ad1 = (const float*)d_in[9];
    const float* b1  = (const float*)d_in[10];
    const float* W2  = (const float*)d_in[11];
    const float* as2 = (const float*)d_in[12];
    const float* ad2 = (const float*)d_in[13];
    const float* b2  = (const float*)d_in[14];
    const float* hw  = (const float*)d_in[15];
    const float* hb  = (const float*)d_in[16];
    float* out = (float*)d_out;

    const int EB = (ET + 255) / 256;
    const int NB = (NN + 255) / 256;
    const int GB = (NN + 63) / 64;    // 64 nodes per 256-thread block
    const int AB = (NN + WPB - 1) / WPB;
    const int PB = (int)(((long long)NN * 32 + 255) / 256);

    // CSR build; gemm0 at capture index 3 to verify the dup-X change
    hist_kernel<<<EB, 256>>>(ei);                                        // 0
    scan1_kernel<<<NBLK, 1024>>>();                                      // 1
    scan3_kernel<<<NB, 256>>>();                                         // 2
    gemm_attn_kernel<128, false><<<GB, 256>>>(x, W0, as0, ad0, nullptr); // 3
    scatter_kernel<<<EB, 256>>>(ei);                                     // 4

    // layer 0 aggregate
    gat_aggregate_kernel<<<AB, 256>>>();

    // layer 1 (input = g_A with bias b0 + relu)
    gemm_attn_kernel<64, true><<<GB, 256>>>(nullptr, W1, as1, ad1, b0);
    gat_aggregate_kernel<<<AB, 256>>>();

    // layer 2 (input = g_A with bias b1 + relu)
    gemm_attn_kernel<64, true><<<GB, 256>>>(nullptr, W2, as2, ad2, b1);
    gat_aggregate_kernel<<<AB, 256>>>();

    // pooling + head (bias b2 + relu fused; also re-zeros g_deg)
    init_out_kernel<<<(GG + 255) / 256, 256>>>(out, hb);
    pool_kernel<<<PB, 256>>>(b2, hw, batch, out);
}